// round 1
// baseline (speedup 1.0000x reference)
#include <cuda_runtime.h>
#include <cuda_bf16.h>
#include <math_constants.h>
#include <cstdint>

// Problem dims
#define B_    4096
#define N0_   2048
#define N1_   1000
#define N2_   500
#define N3_   100
#define C_    100
#define NDIM_ 3
#define NCLS_ 12

// Output layout: concatenated (y0, y1, y2) flattened
#define OUT_Y0 0
#define OUT_Y1 (B_ * NCLS_)                 // 49152
#define OUT_Y2 (B_ * NCLS_ + B_ * C_)       // 458752

// ---------------- scratch (no allocations allowed) ----------------
__device__ float g_h1[B_ * N1_];
__device__ float g_h2[B_ * N2_];
__device__ int   g_idx[B_];
__device__ int   g_cnt[C_];
__device__ int   g_off[C_ + 1];
__device__ int   g_pos[C_];
__device__ int   g_order[B_];

// ---------------- generic fused SGEMM: C = act(A@B + bias) ----------------
// A: [M,K] row-major, B: [K,N] row-major, bias: [N]
// BM=128, BN=64, BK=16, TM=8, TN=4, 256 threads
template <int BM, int BN, int BK, int TM, int TN, bool RELU>
__global__ void __launch_bounds__(256) sgemm_kernel(
    const float* __restrict__ A, const float* __restrict__ Bm,
    const float* __restrict__ bias, float* __restrict__ Cm,
    int M, int N, int K)
{
    __shared__ float As[BK][BM + 1];
    __shared__ float Bs[BK][BN + 1];

    const int tid = threadIdx.x;
    const int blockRow = blockIdx.y * BM;
    const int blockCol = blockIdx.x * BN;
    const int tcol = tid % (BN / TN);   // 0..15
    const int trow = tid / (BN / TN);   // 0..15

    float acc[TM][TN];
    #pragma unroll
    for (int i = 0; i < TM; ++i)
        #pragma unroll
        for (int j = 0; j < TN; ++j) acc[i][j] = 0.f;

    const int numK = (K + BK - 1) / BK;
    for (int kt = 0; kt < numK; ++kt) {
        const int k0 = kt * BK;
        // load A tile (float4 along K, store transposed)
        #pragma unroll
        for (int i = 0; i < (BM * BK) / (256 * 4); ++i) {
            int id  = tid + i * 256;
            int row = id / (BK / 4);
            int k4  = (id % (BK / 4)) * 4;
            int gk  = k0 + k4;
            float4 v = make_float4(0.f, 0.f, 0.f, 0.f);
            if (gk < K)
                v = *reinterpret_cast<const float4*>(&A[(size_t)(blockRow + row) * K + gk]);
            As[k4 + 0][row] = v.x;
            As[k4 + 1][row] = v.y;
            As[k4 + 2][row] = v.z;
            As[k4 + 3][row] = v.w;
        }
        // load B tile (scalar, guarded for N edge)
        #pragma unroll
        for (int i = 0; i < (BK * BN) / 256; ++i) {
            int id = tid + i * 256;
            int bk = id / BN, bn = id % BN;
            int gk = k0 + bk, gn = blockCol + bn;
            Bs[bk][bn] = (gk < K && gn < N) ? Bm[(size_t)gk * N + gn] : 0.f;
        }
        __syncthreads();

        #pragma unroll
        for (int k = 0; k < BK; ++k) {
            float ra[TM], rb[TN];
            #pragma unroll
            for (int i = 0; i < TM; ++i) ra[i] = As[k][trow * TM + i];
            #pragma unroll
            for (int j = 0; j < TN; ++j) rb[j] = Bs[k][tcol * TN + j];
            #pragma unroll
            for (int i = 0; i < TM; ++i)
                #pragma unroll
                for (int j = 0; j < TN; ++j)
                    acc[i][j] += ra[i] * rb[j];
        }
        __syncthreads();
    }

    #pragma unroll
    for (int i = 0; i < TM; ++i) {
        int gm = blockRow + trow * TM + i;
        #pragma unroll
        for (int j = 0; j < TN; ++j) {
            int gn = blockCol + tcol * TN + j;
            if (gn < N) {
                float v = acc[i][j] + bias[gn];
                if (RELU) v = fmaxf(v, 0.f);
                Cm[(size_t)gm * N + gn] = v;
            }
        }
    }
}

// ---------------- y0 = x @ Wcat + bcat  (warp per row) ----------------
__global__ void __launch_bounds__(256) y0_kernel(
    const float* __restrict__ x, const float* __restrict__ Wcat,
    const float* __restrict__ bcat, float* __restrict__ y0)
{
    const int warp = threadIdx.x >> 5, lane = threadIdx.x & 31;
    const int row = blockIdx.x * 8 + warp;
    const float* xr = x + (size_t)row * N0_;
    float acc[NCLS_];
    #pragma unroll
    for (int j = 0; j < NCLS_; ++j) acc[j] = 0.f;

    for (int n = lane; n < N0_; n += 32) {
        float xv = xr[n];
        const float* w = Wcat + (size_t)n * NCLS_;
        #pragma unroll
        for (int j = 0; j < NCLS_; ++j) acc[j] += xv * w[j];
    }
    #pragma unroll
    for (int j = 0; j < NCLS_; ++j) {
        #pragma unroll
        for (int o = 16; o; o >>= 1)
            acc[j] += __shfl_xor_sync(0xffffffffu, acc[j], o);
    }
    if (lane == 0) {
        float* out = y0 + (size_t)row * NCLS_;
        #pragma unroll
        for (int j = 0; j < NCLS_; ++j) out[j] = acc[j] + bcat[j];
    }
}

// ---------------- argmax over y1 rows (warp per row) + class counts ----------------
__global__ void zero_counts_kernel()
{
    int t = threadIdx.x;
    if (t < C_) { g_cnt[t] = 0; }
}

__global__ void argmax_kernel(const float* __restrict__ y1)
{
    const int warp = threadIdx.x >> 5, lane = threadIdx.x & 31;
    const int row = blockIdx.x * 4 + warp;
    const float* r = y1 + (size_t)row * C_;
    float bv = -CUDART_INF_F;
    int   bi = 0x7fffffff;
    for (int j = lane; j < C_; j += 32) {
        float v = r[j];
        if (v > bv || (v == bv && j < bi)) { bv = v; bi = j; }
    }
    #pragma unroll
    for (int o = 16; o; o >>= 1) {
        float ov = __shfl_down_sync(0xffffffffu, bv, o);
        int   oi = __shfl_down_sync(0xffffffffu, bi, o);
        if (ov > bv || (ov == bv && oi < bi)) { bv = ov; bi = oi; }
    }
    if (lane == 0) {
        g_idx[row] = bi;
        atomicAdd(&g_cnt[bi], 1);
    }
}

__global__ void prefix_kernel()
{
    if (threadIdx.x == 0) {
        int s = 0;
        for (int c = 0; c < C_; ++c) {
            g_off[c] = s;
            g_pos[c] = s;
            s += g_cnt[c];
        }
        g_off[C_] = s;
    }
}

__global__ void scatter_kernel()
{
    int b = blockIdx.x * 256 + threadIdx.x;
    int c = g_idx[b];
    int p = atomicAdd(&g_pos[c], 1);
    g_order[p] = b;
}

// ---------------- grouped expert kernel ----------------
// For each class c, process gathered rows in chunks of 32:
//   he = relu(x[row] @ We1[c] + be1[c])   (K=2048 -> 100)
//   y2 = he @ We2[c] + be2[c]             (100 -> 3)
#define EB_ROWS 32
#define EB_BK   32
#define NT      16   // n-values per warp (8 warps cover 128 >= 100)

__global__ void __launch_bounds__(256) expert_kernel(
    const float* __restrict__ x,
    const float* __restrict__ We1, const float* __restrict__ be1,
    const float* __restrict__ We2, const float* __restrict__ be2,
    float* __restrict__ y2out)
{
    const int c     = blockIdx.y;
    const int chunk = blockIdx.x;
    const int start = g_off[c] + chunk * EB_ROWS;
    const int end   = g_off[c + 1];
    if (start >= end) return;

    __shared__ int   rs[EB_ROWS];
    __shared__ float Xs[EB_ROWS][EB_BK + 1];
    __shared__ float Ws[EB_BK * N3_ + 64];     // [k][n], flat; padded for overshoot reads
    __shared__ float He[EB_ROWS][N3_ + 1];
    __shared__ float W2s[N3_ * NDIM_ + 4];

    const int tid  = threadIdx.x;
    const int lane = tid & 31;
    const int warp = tid >> 5;

    if (tid < EB_ROWS) rs[tid] = (start + tid < end) ? g_order[start + tid] : -1;
    for (int i = tid; i < N3_ * NDIM_; i += 256) W2s[i] = We2[(size_t)c * N3_ * NDIM_ + i];
    __syncthreads();

    const int nBase = warp * NT;   // 0,16,...,112 (guarded vs 100 at epilogue)
    float acc[NT];
    #pragma unroll
    for (int j = 0; j < NT; ++j) acc[j] = 0.f;

    const float* W1c = We1 + (size_t)c * N0_ * N3_;
    const float4* Ws4 = reinterpret_cast<const float4*>(Ws);

    for (int kt = 0; kt < N0_ / EB_BK; ++kt) {
        // load X tile: gathered rows, float4 along k
        {
            int r  = tid >> 3;          // 0..31
            int k4 = (tid & 7) * 4;     // 0..28
            int rb = rs[r];
            float4 v = make_float4(0.f, 0.f, 0.f, 0.f);
            if (rb >= 0)
                v = *reinterpret_cast<const float4*>(&x[(size_t)rb * N0_ + kt * EB_BK + k4]);
            Xs[r][k4 + 0] = v.x; Xs[r][k4 + 1] = v.y;
            Xs[r][k4 + 2] = v.z; Xs[r][k4 + 3] = v.w;
        }
        // load W tile: contiguous 3200 floats of We1[c] for this k-chunk
        {
            const float4* src = reinterpret_cast<const float4*>(W1c + (size_t)kt * EB_BK * N3_);
            float4* dst = reinterpret_cast<float4*>(Ws);
            #pragma unroll
            for (int i = 0; i < 4; ++i) {
                int id = tid + i * 256;
                if (id < (EB_BK * N3_) / 4) dst[id] = src[id];
            }
        }
        __syncthreads();

        #pragma unroll 4
        for (int k = 0; k < EB_BK; ++k) {
            float a = Xs[lane][k];   // per-lane row value (conflict-free, stride 33)
            // warp-uniform addresses -> LDS broadcast; float4 to cut LDS count
            #pragma unroll
            for (int j4 = 0; j4 < NT / 4; ++j4) {
                float4 w = Ws4[(k * N3_ + nBase) / 4 + j4];
                acc[j4 * 4 + 0] += a * w.x;
                acc[j4 * 4 + 1] += a * w.y;
                acc[j4 * 4 + 2] += a * w.z;
                acc[j4 * 4 + 3] += a * w.w;
            }
        }
        __syncthreads();
    }

    // he = relu(acc + be1[c])
    #pragma unroll
    for (int j = 0; j < NT; ++j) {
        int n = nBase + j;
        if (n < N3_)
            He[lane][n] = fmaxf(acc[j] + be1[(size_t)c * N3_ + n], 0.f);
    }
    __syncthreads();

    // y2 = he @ We2[c] + be2[c]   (96 dots of length 100)
    if (tid < EB_ROWS * NDIM_) {
        int r = tid / NDIM_, d = tid % NDIM_;
        int rb = rs[r];
        if (rb >= 0) {
            float s = 0.f;
            #pragma unroll 4
            for (int k = 0; k < N3_; ++k) s += He[r][k] * W2s[k * NDIM_ + d];
            y2out[(size_t)rb * NDIM_ + d] = s + be2[(size_t)c * NDIM_ + d];
        }
    }
}

// ---------------- launch ----------------
extern "C" void kernel_launch(void* const* d_in, const int* in_sizes, int n_in,
                              void* d_out, int out_size)
{
    const float* x    = (const float*)d_in[0];
    const float* Wcat = (const float*)d_in[1];
    const float* bcat = (const float*)d_in[2];
    const float* Wb1  = (const float*)d_in[3];
    const float* bb1  = (const float*)d_in[4];
    const float* Wb2  = (const float*)d_in[5];
    const float* bb2  = (const float*)d_in[6];
    const float* Wb3  = (const float*)d_in[7];
    const float* bb3  = (const float*)d_in[8];
    const float* We1  = (const float*)d_in[9];
    const float* be1  = (const float*)d_in[10];
    const float* We2  = (const float*)d_in[11];
    const float* be2  = (const float*)d_in[12];
    float* out = (float*)d_out;

    float* h1;  cudaGetSymbolAddress((void**)&h1, g_h1);
    float* h2;  cudaGetSymbolAddress((void**)&h2, g_h2);

    // bin head
    {
        dim3 grid((N1_ + 63) / 64, B_ / 128);
        sgemm_kernel<128, 64, 16, 8, 4, true><<<grid, 256>>>(x, Wb1, bb1, h1, B_, N1_, N0_);
    }
    {
        dim3 grid((N2_ + 63) / 64, B_ / 128);
        sgemm_kernel<128, 64, 16, 8, 4, true><<<grid, 256>>>(h1, Wb2, bb2, h2, B_, N2_, N1_);
    }
    {
        dim3 grid((C_ + 63) / 64, B_ / 128);
        sgemm_kernel<128, 64, 16, 8, 4, false><<<grid, 256>>>(h2, Wb3, bb3, out + OUT_Y1, B_, C_, N2_);
    }

    // category head
    y0_kernel<<<B_ / 8, 256>>>(x, Wcat, bcat, out + OUT_Y0);

    // argmax + counting sort by class
    zero_counts_kernel<<<1, 128>>>();
    argmax_kernel<<<B_ / 4, 128>>>(out + OUT_Y1);
    prefix_kernel<<<1, 32>>>();
    scatter_kernel<<<B_ / 256, 256>>>();

    // selected-expert evaluation only
    {
        dim3 grid(B_ / EB_ROWS, C_);   // (chunk, class); empty blocks exit immediately
        expert_kernel<<<grid, 256>>>(x, We1, be1, We2, be2, out + OUT_Y2);
    }
}

// round 3
// speedup vs baseline: 1.1250x; 1.1250x over previous
#include <cuda_runtime.h>
#include <cuda_bf16.h>
#include <math_constants.h>
#include <cstdint>

// Problem dims
#define B_    4096
#define N0_   2048
#define N1_   1000
#define N1P   1024
#define N2_   500
#define N2P   512
#define N3_   100
#define C_    100
#define NDIM_ 3
#define NCLS_ 12

// Output layout: concatenated (y0, y1, y2) flattened
#define OUT_Y0 0
#define OUT_Y1 (B_ * NCLS_)
#define OUT_Y2 (B_ * NCLS_ + B_ * C_)

// ---------------- scratch (no allocations allowed) ----------------
__device__ __nv_bfloat16 g_xhi[B_ * N0_];
__device__ __nv_bfloat16 g_xlo[B_ * N0_];
__device__ __nv_bfloat16 g_w1hi[N0_ * N1P];
__device__ __nv_bfloat16 g_w1lo[N0_ * N1P];
__device__ __nv_bfloat16 g_h1hi[B_ * N1P];
__device__ __nv_bfloat16 g_h1lo[B_ * N1P];
__device__ __nv_bfloat16 g_w2hi[N1P * N2P];
__device__ __nv_bfloat16 g_w2lo[N1P * N2P];
__device__ float g_h2[B_ * N2P];
__device__ int   g_idx[B_];
__device__ int   g_cnt[C_];
__device__ int   g_off[C_ + 1];
__device__ int   g_pos[C_];
__device__ int   g_order[B_];

// ---------------- fp32 -> (hi, lo) bf16 split with zero padding ----------------
__global__ void __launch_bounds__(256) split_pad_kernel(
    const float* __restrict__ in, __nv_bfloat16* __restrict__ hi,
    __nv_bfloat16* __restrict__ lo, int Rin, int Cin, int Rout, int Cout)
{
    int i = blockIdx.x * 256 + threadIdx.x;
    int total = Rout * Cout;
    if (i >= total) return;
    int r = i / Cout, c = i % Cout;
    float v = (r < Rin && c < Cin) ? in[(size_t)r * Cin + c] : 0.f;
    __nv_bfloat16 h = __float2bfloat16(v);
    hi[i] = h;
    lo[i] = __float2bfloat16(v - __bfloat162float(h));
}

// ---------------- mma helper ----------------
__device__ __forceinline__ void mma16816(float* c, const uint32_t* a, const uint32_t* b)
{
    asm volatile(
        "mma.sync.aligned.m16n8k16.row.col.f32.bf16.bf16.f32 "
        "{%0,%1,%2,%3}, {%4,%5,%6,%7}, {%8,%9}, {%0,%1,%2,%3};\n"
        : "+f"(c[0]), "+f"(c[1]), "+f"(c[2]), "+f"(c[3])
        : "r"(a[0]), "r"(a[1]), "r"(a[2]), "r"(a[3]), "r"(b[0]), "r"(b[1]));
}

// ---------------- split-bf16 tensor-core GEMM ----------------
// C = relu(A@B + bias), A = Ahi+Alo [M][K], B = Bhi+Blo [K][N] (N,K padded, no guards)
// EPI=0: write fp32 C (zero for col>=Nvalid). EPI=1: write bf16 hi/lo C.
// Block tile 128x64x32, 8 warps (4x2), warp tile 32x32, mma m16n8k16, 4 products.
template <int EPI>
__global__ void __launch_bounds__(256) mma_gemm_kernel(
    const __nv_bfloat16* __restrict__ Ahi, const __nv_bfloat16* __restrict__ Alo,
    const __nv_bfloat16* __restrict__ Bhi, const __nv_bfloat16* __restrict__ Blo,
    const float* __restrict__ bias, int Nvalid,
    float* __restrict__ Cf, __nv_bfloat16* __restrict__ Chi, __nv_bfloat16* __restrict__ Clo,
    int M, int N, int K)
{
    __shared__ __align__(16) __nv_bfloat16 sA[2][128][40];
    __shared__ __align__(16) __nv_bfloat16 sB[2][64][40];   // transposed [n][k]

    const int tid  = threadIdx.x;
    const int lane = tid & 31;
    const int w    = tid >> 5;
    const int wm   = (w >> 1) * 32;
    const int wn   = (w & 1) * 32;
    const int rowBase = blockIdx.y * 128;
    const int colBase = blockIdx.x * 64;

    const int bkk  = tid >> 3;          // B load: k row 0..31
    const int bseg = tid & 7;           // 8 bf16 along n

    float acc[2][4][4];
    #pragma unroll
    for (int mt = 0; mt < 2; ++mt)
        #pragma unroll
        for (int nt = 0; nt < 4; ++nt)
            #pragma unroll
            for (int q = 0; q < 4; ++q) acc[mt][nt][q] = 0.f;

    const int KT = K >> 5;
    uint4 pa[2][2], pb[2];

    // prologue: fetch chunk 0
    #pragma unroll
    for (int m = 0; m < 2; ++m) {
        const __nv_bfloat16* srcA = m ? Alo : Ahi;
        #pragma unroll
        for (int i = 0; i < 2; ++i) {
            int id = tid + i * 256;
            pa[m][i] = *reinterpret_cast<const uint4*>(
                srcA + (size_t)(rowBase + (id >> 2)) * K + (id & 3) * 8);
        }
        const __nv_bfloat16* srcB = m ? Blo : Bhi;
        pb[m] = *reinterpret_cast<const uint4*>(
            srcB + (size_t)bkk * N + colBase + bseg * 8);
    }
    #pragma unroll
    for (int m = 0; m < 2; ++m) {
        #pragma unroll
        for (int i = 0; i < 2; ++i) {
            int id = tid + i * 256;
            *reinterpret_cast<uint4*>(&sA[m][id >> 2][(id & 3) * 8]) = pa[m][i];
        }
        __nv_bfloat16 t[8];
        *reinterpret_cast<uint4*>(t) = pb[m];
        #pragma unroll
        for (int j = 0; j < 8; ++j) sB[m][bseg * 8 + j][bkk] = t[j];
    }
    __syncthreads();

    for (int kt = 0; kt < KT; ++kt) {
        const bool hasNext = (kt + 1) < KT;
        if (hasNext) {
            int k0 = (kt + 1) * 32;
            #pragma unroll
            for (int m = 0; m < 2; ++m) {
                const __nv_bfloat16* srcA = m ? Alo : Ahi;
                #pragma unroll
                for (int i = 0; i < 2; ++i) {
                    int id = tid + i * 256;
                    pa[m][i] = *reinterpret_cast<const uint4*>(
                        srcA + (size_t)(rowBase + (id >> 2)) * K + k0 + (id & 3) * 8);
                }
                const __nv_bfloat16* srcB = m ? Blo : Bhi;
                pb[m] = *reinterpret_cast<const uint4*>(
                    srcB + (size_t)(k0 + bkk) * N + colBase + bseg * 8);
            }
        }

        // compute on current shared tiles
        #pragma unroll
        for (int ks = 0; ks < 32; ks += 16) {
            uint32_t af[2][2][4];   // [mat][mt][reg]
            const int kc = ks + (lane & 3) * 2;
            #pragma unroll
            for (int m = 0; m < 2; ++m) {
                #pragma unroll
                for (int mt = 0; mt < 2; ++mt) {
                    int r0 = wm + mt * 16 + (lane >> 2);
                    af[m][mt][0] = *reinterpret_cast<const uint32_t*>(&sA[m][r0][kc]);
                    af[m][mt][1] = *reinterpret_cast<const uint32_t*>(&sA[m][r0 + 8][kc]);
                    af[m][mt][2] = *reinterpret_cast<const uint32_t*>(&sA[m][r0][kc + 8]);
                    af[m][mt][3] = *reinterpret_cast<const uint32_t*>(&sA[m][r0 + 8][kc + 8]);
                }
            }
            #pragma unroll
            for (int nt = 0; nt < 4; ++nt) {
                int cn = wn + nt * 8 + (lane >> 2);
                uint32_t bh[2], bl[2];
                bh[0] = *reinterpret_cast<const uint32_t*>(&sB[0][cn][kc]);
                bh[1] = *reinterpret_cast<const uint32_t*>(&sB[0][cn][kc + 8]);
                bl[0] = *reinterpret_cast<const uint32_t*>(&sB[1][cn][kc]);
                bl[1] = *reinterpret_cast<const uint32_t*>(&sB[1][cn][kc + 8]);
                #pragma unroll
                for (int mt = 0; mt < 2; ++mt) {
                    mma16816(acc[mt][nt], af[0][mt], bh);
                    mma16816(acc[mt][nt], af[0][mt], bl);
                    mma16816(acc[mt][nt], af[1][mt], bh);
                    mma16816(acc[mt][nt], af[1][mt], bl);
                }
            }
        }
        __syncthreads();

        if (hasNext) {
            #pragma unroll
            for (int m = 0; m < 2; ++m) {
                #pragma unroll
                for (int i = 0; i < 2; ++i) {
                    int id = tid + i * 256;
                    *reinterpret_cast<uint4*>(&sA[m][id >> 2][(id & 3) * 8]) = pa[m][i];
                }
                __nv_bfloat16 t[8];
                *reinterpret_cast<uint4*>(t) = pb[m];
                #pragma unroll
                for (int j = 0; j < 8; ++j) sB[m][bseg * 8 + j][bkk] = t[j];
            }
            __syncthreads();
        }
    }

    // epilogue
    #pragma unroll
    for (int mt = 0; mt < 2; ++mt) {
        #pragma unroll
        for (int nt = 0; nt < 4; ++nt) {
            int gm0 = rowBase + wm + mt * 16 + (lane >> 2);
            int gn  = colBase + wn + nt * 8 + (lane & 3) * 2;
            bool valid = gn < Nvalid;
            float b0 = valid ? bias[gn] : 0.f;
            float b1 = valid ? bias[gn + 1] : 0.f;
            #pragma unroll
            for (int half = 0; half < 2; ++half) {
                int gm = gm0 + half * 8;
                float v0 = valid ? fmaxf(acc[mt][nt][half * 2 + 0] + b0, 0.f) : 0.f;
                float v1 = valid ? fmaxf(acc[mt][nt][half * 2 + 1] + b1, 0.f) : 0.f;
                if (EPI == 0) {
                    float2 o = make_float2(v0, v1);
                    *reinterpret_cast<float2*>(&Cf[(size_t)gm * N + gn]) = o;
                } else {
                    __nv_bfloat16 h0 = __float2bfloat16(v0);
                    __nv_bfloat16 h1 = __float2bfloat16(v1);
                    __nv_bfloat162 hp; hp.x = h0; hp.y = h1;
                    *reinterpret_cast<__nv_bfloat162*>(&Chi[(size_t)gm * N + gn]) = hp;
                    __nv_bfloat162 lp;
                    lp.x = __float2bfloat16(v0 - __bfloat162float(h0));
                    lp.y = __float2bfloat16(v1 - __bfloat162float(h1));
                    *reinterpret_cast<__nv_bfloat162*>(&Clo[(size_t)gm * N + gn]) = lp;
                }
            }
        }
    }
}

// ---------------- SIMT SGEMM (GEMM3): C = A@B + bias ----------------
template <int BM, int BN, int BK, int TM, int TN, bool RELU>
__global__ void __launch_bounds__(256) sgemm_kernel(
    const float* __restrict__ A, int lda, const float* __restrict__ Bm,
    const float* __restrict__ bias, float* __restrict__ Cm,
    int M, int N, int K)
{
    __shared__ float As[BK][BM + 1];
    __shared__ float Bs[BK][BN + 1];

    const int tid = threadIdx.x;
    const int blockRow = blockIdx.y * BM;
    const int blockCol = blockIdx.x * BN;
    const int tcol = tid % (BN / TN);
    const int trow = tid / (BN / TN);

    float acc[TM][TN];
    #pragma unroll
    for (int i = 0; i < TM; ++i)
        #pragma unroll
        for (int j = 0; j < TN; ++j) acc[i][j] = 0.f;

    const int numK = (K + BK - 1) / BK;
    for (int kt = 0; kt < numK; ++kt) {
        const int k0 = kt * BK;
        #pragma unroll
        for (int i = 0; i < (BM * BK) / (256 * 4); ++i) {
            int id  = tid + i * 256;
            int row = id / (BK / 4);
            int k4  = (id % (BK / 4)) * 4;
            int gk  = k0 + k4;
            float4 v = make_float4(0.f, 0.f, 0.f, 0.f);
            if (gk < K)
                v = *reinterpret_cast<const float4*>(&A[(size_t)(blockRow + row) * lda + gk]);
            As[k4 + 0][row] = v.x;
            As[k4 + 1][row] = v.y;
            As[k4 + 2][row] = v.z;
            As[k4 + 3][row] = v.w;
        }
        #pragma unroll
        for (int i = 0; i < (BK * BN) / 256; ++i) {
            int id = tid + i * 256;
            int bk = id / BN, bn = id % BN;
            int gk = k0 + bk, gn = blockCol + bn;
            Bs[bk][bn] = (gk < K && gn < N) ? Bm[(size_t)gk * N + gn] : 0.f;
        }
        __syncthreads();

        #pragma unroll
        for (int k = 0; k < BK; ++k) {
            float ra[TM], rb[TN];
            #pragma unroll
            for (int i = 0; i < TM; ++i) ra[i] = As[k][trow * TM + i];
            #pragma unroll
            for (int j = 0; j < TN; ++j) rb[j] = Bs[k][tcol * TN + j];
            #pragma unroll
            for (int i = 0; i < TM; ++i)
                #pragma unroll
                for (int j = 0; j < TN; ++j)
                    acc[i][j] += ra[i] * rb[j];
        }
        __syncthreads();
    }

    #pragma unroll
    for (int i = 0; i < TM; ++i) {
        int gm = blockRow + trow * TM + i;
        #pragma unroll
        for (int j = 0; j < TN; ++j) {
            int gn = blockCol + tcol * TN + j;
            if (gn < N) {
                float v = acc[i][j] + bias[gn];
                if (RELU) v = fmaxf(v, 0.f);
                Cm[(size_t)gm * N + gn] = v;
            }
        }
    }
}

// ---------------- y0 = x @ Wcat + bcat (64-row tiles) ----------------
__global__ void __launch_bounds__(256) y0_kernel(
    const float* __restrict__ x, const float* __restrict__ Wcat,
    const float* __restrict__ bcat, float* __restrict__ y0)
{
    __shared__ __align__(16) float xs[64][36];
    __shared__ float ws[32][NCLS_];

    const int tid  = threadIdx.x;
    const int row0 = blockIdx.x * 64;
    const int r    = tid >> 2;
    const int q    = tid & 3;

    float acc[3] = {0.f, 0.f, 0.f};

    for (int kt = 0; kt < N0_ / 32; ++kt) {
        #pragma unroll
        for (int i = 0; i < 2; ++i) {
            int id = tid + i * 256;
            int rr = id >> 3, seg = id & 7;
            float4 v = *reinterpret_cast<const float4*>(
                &x[(size_t)(row0 + rr) * N0_ + kt * 32 + seg * 4]);
            *reinterpret_cast<float4*>(&xs[rr][seg * 4]) = v;
        }
        #pragma unroll
        for (int i = 0; i < 2; ++i) {
            int id = tid + i * 256;
            if (id < 32 * NCLS_) ((float*)ws)[id] = Wcat[kt * 32 * NCLS_ + id];
        }
        __syncthreads();

        #pragma unroll 8
        for (int k = 0; k < 32; ++k) {
            float xv = xs[r][k];
            acc[0] += xv * ws[k][q];
            acc[1] += xv * ws[k][q + 4];
            acc[2] += xv * ws[k][q + 8];
        }
        __syncthreads();
    }

    float* out = y0 + (size_t)(row0 + r) * NCLS_;
    out[q]     = acc[0] + bcat[q];
    out[q + 4] = acc[1] + bcat[q + 4];
    out[q + 8] = acc[2] + bcat[q + 8];
}

// ---------------- argmax + counting sort ----------------
__global__ void zero_counts_kernel()
{
    int t = threadIdx.x;
    if (t < C_) g_cnt[t] = 0;
}

__global__ void argmax_kernel(const float* __restrict__ y1)
{
    const int warp = threadIdx.x >> 5, lane = threadIdx.x & 31;
    const int row = blockIdx.x * 4 + warp;
    const float* r = y1 + (size_t)row * C_;
    float bv = -CUDART_INF_F;
    int   bi = 0x7fffffff;
    for (int j = lane; j < C_; j += 32) {
        float v = r[j];
        if (v > bv || (v == bv && j < bi)) { bv = v; bi = j; }
    }
    #pragma unroll
    for (int o = 16; o; o >>= 1) {
        float ov = __shfl_down_sync(0xffffffffu, bv, o);
        int   oi = __shfl_down_sync(0xffffffffu, bi, o);
        if (ov > bv || (ov == bv && oi < bi)) { bv = ov; bi = oi; }
    }
    if (lane == 0) {
        g_idx[row] = bi;
        atomicAdd(&g_cnt[bi], 1);
    }
}

__global__ void prefix_kernel()
{
    if (threadIdx.x == 0) {
        int s = 0;
        for (int c = 0; c < C_; ++c) {
            g_off[c] = s;
            g_pos[c] = s;
            s += g_cnt[c];
        }
        g_off[C_] = s;
    }
}

__global__ void scatter_kernel()
{
    int b = blockIdx.x * 256 + threadIdx.x;
    int c = g_idx[b];
    int p = atomicAdd(&g_pos[c], 1);
    g_order[p] = b;
}

// ---------------- grouped expert kernel ----------------
#define EB_ROWS 32
#define EB_BK   32
#define NT      16

__global__ void __launch_bounds__(256) expert_kernel(
    const float* __restrict__ x,
    const float* __restrict__ We1, const float* __restrict__ be1,
    const float* __restrict__ We2, const float* __restrict__ be2,
    float* __restrict__ y2out)
{
    const int c     = blockIdx.y;
    const int chunk = blockIdx.x;
    const int start = g_off[c] + chunk * EB_ROWS;
    const int end   = g_off[c + 1];
    if (start >= end) return;

    __shared__ int   rs[EB_ROWS];
    __shared__ float Xs[EB_ROWS][EB_BK + 1];
    __shared__ float Ws[EB_BK * N3_ + 64];
    __shared__ float He[EB_ROWS][N3_ + 1];
    __shared__ float W2s[N3_ * NDIM_ + 4];

    const int tid  = threadIdx.x;
    const int lane = tid & 31;
    const int warp = tid >> 5;

    if (tid < EB_ROWS) rs[tid] = (start + tid < end) ? g_order[start + tid] : -1;
    for (int i = tid; i < N3_ * NDIM_; i += 256) W2s[i] = We2[(size_t)c * N3_ * NDIM_ + i];
    __syncthreads();

    const int nBase = warp * NT;
    float acc[NT];
    #pragma unroll
    for (int j = 0; j < NT; ++j) acc[j] = 0.f;

    const float* W1c = We1 + (size_t)c * N0_ * N3_;
    const float4* Ws4 = reinterpret_cast<const float4*>(Ws);

    for (int kt = 0; kt < N0_ / EB_BK; ++kt) {
        {
            int r  = tid >> 3;
            int k4 = (tid & 7) * 4;
            int rb = rs[r];
            float4 v = make_float4(0.f, 0.f, 0.f, 0.f);
            if (rb >= 0)
                v = *reinterpret_cast<const float4*>(&x[(size_t)rb * N0_ + kt * EB_BK + k4]);
            Xs[r][k4 + 0] = v.x; Xs[r][k4 + 1] = v.y;
            Xs[r][k4 + 2] = v.z; Xs[r][k4 + 3] = v.w;
        }
        {
            const float4* src = reinterpret_cast<const float4*>(W1c + (size_t)kt * EB_BK * N3_);
            float4* dst = reinterpret_cast<float4*>(Ws);
            #pragma unroll
            for (int i = 0; i < 4; ++i) {
                int id = tid + i * 256;
                if (id < (EB_BK * N3_) / 4) dst[id] = src[id];
            }
        }
        __syncthreads();

        #pragma unroll 4
        for (int k = 0; k < EB_BK; ++k) {
            float a = Xs[lane][k];
            #pragma unroll
            for (int j4 = 0; j4 < NT / 4; ++j4) {
                float4 wv = Ws4[(k * N3_ + nBase) / 4 + j4];
                acc[j4 * 4 + 0] += a * wv.x;
                acc[j4 * 4 + 1] += a * wv.y;
                acc[j4 * 4 + 2] += a * wv.z;
                acc[j4 * 4 + 3] += a * wv.w;
            }
        }
        __syncthreads();
    }

    #pragma unroll
    for (int j = 0; j < NT; ++j) {
        int n = nBase + j;
        if (n < N3_)
            He[lane][n] = fmaxf(acc[j] + be1[(size_t)c * N3_ + n], 0.f);
    }
    __syncthreads();

    if (tid < EB_ROWS * NDIM_) {
        int r = tid / NDIM_, d = tid % NDIM_;
        int rb = rs[r];
        if (rb >= 0) {
            float s = 0.f;
            #pragma unroll 4
            for (int k = 0; k < N3_; ++k) s += He[r][k] * W2s[k * NDIM_ + d];
            y2out[(size_t)rb * NDIM_ + d] = s + be2[(size_t)c * NDIM_ + d];
        }
    }
}

// ---------------- launch ----------------
extern "C" void kernel_launch(void* const* d_in, const int* in_sizes, int n_in,
                              void* d_out, int out_size)
{
    const float* x    = (const float*)d_in[0];
    const float* Wcat = (const float*)d_in[1];
    const float* bcat = (const float*)d_in[2];
    const float* Wb1  = (const float*)d_in[3];
    const float* bb1  = (const float*)d_in[4];
    const float* Wb2  = (const float*)d_in[5];
    const float* bb2  = (const float*)d_in[6];
    const float* Wb3  = (const float*)d_in[7];
    const float* bb3  = (const float*)d_in[8];
    const float* We1  = (const float*)d_in[9];
    const float* be1  = (const float*)d_in[10];
    const float* We2  = (const float*)d_in[11];
    const float* be2  = (const float*)d_in[12];
    float* out = (float*)d_out;

    __nv_bfloat16 *xhi, *xlo, *w1hi, *w1lo, *h1hi, *h1lo, *w2hi, *w2lo;
    float* h2;
    cudaGetSymbolAddress((void**)&xhi,  g_xhi);
    cudaGetSymbolAddress((void**)&xlo,  g_xlo);
    cudaGetSymbolAddress((void**)&w1hi, g_w1hi);
    cudaGetSymbolAddress((void**)&w1lo, g_w1lo);
    cudaGetSymbolAddress((void**)&h1hi, g_h1hi);
    cudaGetSymbolAddress((void**)&h1lo, g_h1lo);
    cudaGetSymbolAddress((void**)&w2hi, g_w2hi);
    cudaGetSymbolAddress((void**)&w2lo, g_w2lo);
    cudaGetSymbolAddress((void**)&h2,   g_h2);

    // splits
    split_pad_kernel<<<(B_ * N0_ + 255) / 256, 256>>>(x, xhi, xlo, B_, N0_, B_, N0_);
    split_pad_kernel<<<(N0_ * N1P + 255) / 256, 256>>>(Wb1, w1hi, w1lo, N0_, N1_, N0_, N1P);
    split_pad_kernel<<<(N1P * N2P + 255) / 256, 256>>>(Wb2, w2hi, w2lo, N1_, N2_, N1P, N2P);

    // bin head on tensor cores
    {
        dim3 grid(N1P / 64, B_ / 128);
        mma_gemm_kernel<1><<<grid, 256>>>(xhi, xlo, w1hi, w1lo, bb1, N1_,
                                          nullptr, h1hi, h1lo, B_, N1P, N0_);
    }
    {
        dim3 grid(N2P / 64, B_ / 128);
        mma_gemm_kernel<0><<<grid, 256>>>(h1hi, h1lo, w2hi, w2lo, bb2, N2_,
                                          h2, nullptr, nullptr, B_, N2P, N1P);
    }
    {
        dim3 grid((C_ + 63) / 64, B_ / 128);
        sgemm_kernel<128, 64, 16, 8, 4, false><<<grid, 256>>>(
            h2, N2P, Wb3, bb3, out + OUT_Y1, B_, C_, N2_);
    }

    // category head
    y0_kernel<<<B_ / 64, 256>>>(x, Wcat, bcat, out + OUT_Y0);

    // argmax + counting sort
    zero_counts_kernel<<<1, 128>>>();
    argmax_kernel<<<B_ / 4, 128>>>(out + OUT_Y1);
    prefix_kernel<<<1, 32>>>();
    scatter_kernel<<<B_ / 256, 256>>>();

    // selected-expert evaluation
    {
        dim3 grid(B_ / EB_ROWS, C_);
        expert_kernel<<<grid, 256>>>(x, We1, be1, We2, be2, out + OUT_Y2);
    }
}

// round 5
// speedup vs baseline: 1.4989x; 1.3324x over previous
#include <cuda_runtime.h>
#include <cuda_bf16.h>
#include <math_constants.h>
#include <cstdint>

// Problem dims
#define B_    4096
#define N0_   2048
#define N1_   1000
#define N1P   1024
#define N2_   500
#define N2P   512
#define N3_   100
#define C_    100
#define NDIM_ 3
#define NCLS_ 12

// Output layout: concatenated (y0, y1, y2) flattened
#define OUT_Y0 0
#define OUT_Y1 (B_ * NCLS_)
#define OUT_Y2 (B_ * NCLS_ + B_ * C_)

// ---------------- scratch (no allocations allowed) ----------------
__device__ uint32_t g_xp[B_ * N0_];        // x packed hi|lo<<16
__device__ uint32_t g_w1t[N1P * N0_];      // Wb1^T packed [N1P][N0]
__device__ uint32_t g_h1p[B_ * N1P];       // h1 packed
__device__ uint32_t g_w2t[N2P * N1P];      // Wb2^T packed [N2P][N1P]
__device__ uint32_t g_h2p[B_ * N2P];       // h2 packed
__device__ uint32_t g_w3t[128 * N2P];      // Wb3^T packed [128][N2P]
__device__ int   g_idx[B_];
__device__ int   g_cnt[C_];
__device__ int   g_off[C_ + 1];
__device__ int   g_pos[C_];
__device__ int   g_order[B_];

// ---------------- helpers ----------------
__device__ __forceinline__ uint32_t pack_split(float v)
{
    __nv_bfloat16 h = __float2bfloat16(v);
    __nv_bfloat16 l = __float2bfloat16(v - __bfloat162float(h));
    return (uint32_t)__bfloat16_as_ushort(h) | ((uint32_t)__bfloat16_as_ushort(l) << 16);
}

__device__ __forceinline__ uint32_t smem_u32(const void* p)
{
    uint32_t a;
    asm("{ .reg .u64 t; cvta.to.shared.u64 t, %1; cvt.u32.u64 %0, t; }" : "=r"(a) : "l"(p));
    return a;
}

__device__ __forceinline__ void mma16816(float* c, const uint32_t* a, const uint32_t* b)
{
    asm volatile(
        "mma.sync.aligned.m16n8k16.row.col.f32.bf16.bf16.f32 "
        "{%0,%1,%2,%3}, {%4,%5,%6,%7}, {%8,%9}, {%0,%1,%2,%3};\n"
        : "+f"(c[0]), "+f"(c[1]), "+f"(c[2]), "+f"(c[3])
        : "r"(a[0]), "r"(a[1]), "r"(a[2]), "r"(a[3]), "r"(b[0]), "r"(b[1]));
}

__device__ __forceinline__ void ldsm4(uint32_t* r, uint32_t a)
{
    asm volatile("ldmatrix.sync.aligned.m8n8.x4.shared.b16 {%0,%1,%2,%3}, [%4];"
                 : "=r"(r[0]), "=r"(r[1]), "=r"(r[2]), "=r"(r[3]) : "r"(a));
}

// ---------------- preprocessing kernels ----------------
__global__ void __launch_bounds__(256) split_pack_kernel(
    const float* __restrict__ in, uint32_t* __restrict__ out, int n)
{
    int i = blockIdx.x * 256 + threadIdx.x;
    if (i < n) out[i] = pack_split(in[i]);
}

// in: W [Kin][Nin] fp32 row-major -> out: [NP][KP] packed u32 (transposed, zero-padded)
__global__ void __launch_bounds__(256) transpose_split_pack_kernel(
    const float* __restrict__ in, uint32_t* __restrict__ out,
    int Kin, int Nin, int KP, int NP)
{
    __shared__ uint32_t t[32][33];
    int k0 = blockIdx.x * 32, n0 = blockIdx.y * 32;
    #pragma unroll
    for (int j = 0; j < 4; ++j) {
        int k = k0 + threadIdx.y + j * 8, n = n0 + threadIdx.x;
        float v = (k < Kin && n < Nin) ? in[(size_t)k * Nin + n] : 0.f;
        t[threadIdx.y + j * 8][threadIdx.x] = pack_split(v);
    }
    __syncthreads();
    #pragma unroll
    for (int j = 0; j < 4; ++j) {
        int n = n0 + threadIdx.y + j * 8, k = k0 + threadIdx.x;
        out[(size_t)n * KP + k] = t[threadIdx.x][threadIdx.y + j * 8];
    }
}

// ---------------- split-bf16 mma GEMM (3-product) ----------------
// A: [M][K] packed u32, B: [N][K] packed u32 (pre-transposed weights).
// Block tile 128x64x32, 8 warps (4x2), warp tile 32x32.
// D = Ah*Bh + Ah*Bl + Al*Bh (lo*lo dropped, ~2^-16 relative).
// EPI=0: fp32 out with ldC stride, store pairs while gn+1 < Nvalid.
// EPI=1: packed u32 out, stride N, zeros for gn >= Nvalid.
template <int EPI, bool RELU>
__global__ void __launch_bounds__(256, 2) mma_gemm_kernel(
    const uint32_t* __restrict__ Ap, const uint32_t* __restrict__ Bp,
    const float* __restrict__ bias,
    float* __restrict__ Cf, uint32_t* __restrict__ Cp,
    int ldC, int Nvalid, int N, int K)
{
    __shared__ __align__(16) __nv_bfloat16 sA[2][128][40];
    __shared__ __align__(16) __nv_bfloat16 sB[2][64][40];

    const int tid  = threadIdx.x;
    const int lane = tid & 31;
    const int w    = tid >> 5;
    const int wm   = (w >> 1) * 32;
    const int wn   = (w & 1) * 32;
    const int rowBase = blockIdx.y * 128;
    const int colBase = blockIdx.x * 64;

    float acc[2][4][4];
    #pragma unroll
    for (int mt = 0; mt < 2; ++mt)
        #pragma unroll
        for (int nt = 0; nt < 4; ++nt)
            #pragma unroll
            for (int q = 0; q < 4; ++q) acc[mt][nt][q] = 0.f;

    const int KT = K >> 5;
    uint4 pa[4], pb[2];

    // -- tile fetch helpers (reg prefetch + unpack-store) --
    const int arow = tid >> 3;       // base row for A ids
    const int aseg = tid & 7;

    auto fetch = [&](int kt) {
        #pragma unroll
        for (int i = 0; i < 4; ++i) {
            int id = tid + i * 256;
            pa[i] = *reinterpret_cast<const uint4*>(
                Ap + (size_t)(rowBase + (id >> 3)) * K + kt * 32 + (id & 7) * 4);
        }
        #pragma unroll
        for (int i = 0; i < 2; ++i) {
            int id = tid + i * 256;
            pb[i] = *reinterpret_cast<const uint4*>(
                Bp + (size_t)(colBase + (id >> 3)) * K + kt * 32 + (id & 7) * 4);
        }
    };
    auto store = [&]() {
        #pragma unroll
        for (int i = 0; i < 4; ++i) {
            int id = tid + i * 256;
            int row = id >> 3, seg = id & 7;
            uint4 v = pa[i];
            uint32_t h0 = (v.x & 0xffffu) | (v.y << 16);
            uint32_t l0 = (v.x >> 16) | (v.y & 0xffff0000u);
            uint32_t h1 = (v.z & 0xffffu) | (v.w << 16);
            uint32_t l1 = (v.z >> 16) | (v.w & 0xffff0000u);
            *reinterpret_cast<uint2*>(&sA[0][row][seg * 4]) = make_uint2(h0, h1);
            *reinterpret_cast<uint2*>(&sA[1][row][seg * 4]) = make_uint2(l0, l1);
        }
        #pragma unroll
        for (int i = 0; i < 2; ++i) {
            int id = tid + i * 256;
            int row = id >> 3, seg = id & 7;
            uint4 v = pb[i];
            uint32_t h0 = (v.x & 0xffffu) | (v.y << 16);
            uint32_t l0 = (v.x >> 16) | (v.y & 0xffff0000u);
            uint32_t h1 = (v.z & 0xffffu) | (v.w << 16);
            uint32_t l1 = (v.z >> 16) | (v.w & 0xffff0000u);
            *reinterpret_cast<uint2*>(&sB[0][row][seg * 4]) = make_uint2(h0, h1);
            *reinterpret_cast<uint2*>(&sB[1][row][seg * 4]) = make_uint2(l0, l1);
        }
    };

    fetch(0);
    store();
    __syncthreads();

    for (int kt = 0; kt < KT; ++kt) {
        const bool hasNext = (kt + 1) < KT;
        if (hasNext) fetch(kt + 1);

        #pragma unroll
        for (int ks = 0; ks < 32; ks += 16) {
            uint32_t ah[2][4], al[2][4];
            #pragma unroll
            for (int mt = 0; mt < 2; ++mt) {
                uint32_t ad = smem_u32(&sA[0][wm + mt * 16 + (lane & 15)][ks + (lane >> 4) * 8]);
                ldsm4(ah[mt], ad);
                ad = smem_u32(&sA[1][wm + mt * 16 + (lane & 15)][ks + (lane >> 4) * 8]);
                ldsm4(al[mt], ad);
            }
            uint32_t bh0[4], bh1[4], bl0[4], bl1[4];
            {
                uint32_t bd = smem_u32(&sB[0][wn + lane][ks]);
                ldsm4(bh0, bd);
                bd = smem_u32(&sB[0][wn + lane][ks + 8]);
                ldsm4(bh1, bd);
                bd = smem_u32(&sB[1][wn + lane][ks]);
                ldsm4(bl0, bd);
                bd = smem_u32(&sB[1][wn + lane][ks + 8]);
                ldsm4(bl1, bd);
            }
            #pragma unroll
            for (int nt = 0; nt < 4; ++nt) {
                uint32_t bhp[2] = {bh0[nt], bh1[nt]};
                uint32_t blp[2] = {bl0[nt], bl1[nt]};
                #pragma unroll
                for (int mt = 0; mt < 2; ++mt) {
                    mma16816(acc[mt][nt], ah[mt], bhp);
                    mma16816(acc[mt][nt], ah[mt], blp);
                    mma16816(acc[mt][nt], al[mt], bhp);
                }
            }
        }
        __syncthreads();

        if (hasNext) {
            store();
            __syncthreads();
        }
    }

    // epilogue
    #pragma unroll
    for (int mt = 0; mt < 2; ++mt) {
        #pragma unroll
        for (int nt = 0; nt < 4; ++nt) {
            int gm0 = rowBase + wm + mt * 16 + (lane >> 2);
            int gn  = colBase + wn + nt * 8 + (lane & 3) * 2;
            bool valid = gn < Nvalid;
            float b0 = valid ? bias[gn] : 0.f;
            float b1 = valid ? bias[gn + 1] : 0.f;
            #pragma unroll
            for (int half = 0; half < 2; ++half) {
                int gm = gm0 + half * 8;
                float v0 = valid ? (acc[mt][nt][half * 2 + 0] + b0) : 0.f;
                float v1 = valid ? (acc[mt][nt][half * 2 + 1] + b1) : 0.f;
                if (RELU) { v0 = fmaxf(v0, 0.f); v1 = fmaxf(v1, 0.f); }
                if (EPI == 1) {
                    uint2 o = make_uint2(pack_split(v0), pack_split(v1));
                    *reinterpret_cast<uint2*>(Cp + (size_t)gm * N + gn) = o;
                } else {
                    if (gn + 1 < Nvalid) {
                        float2 o = make_float2(v0, v1);
                        *reinterpret_cast<float2*>(Cf + (size_t)gm * ldC + gn) = o;
                    }
                }
            }
        }
    }
    (void)arow; (void)aseg;
}

// ---------------- y0 = x @ Wcat + bcat (64-row tiles) ----------------
__global__ void __launch_bounds__(256) y0_kernel(
    const float* __restrict__ x, const float* __restrict__ Wcat,
    const float* __restrict__ bcat, float* __restrict__ y0)
{
    __shared__ __align__(16) float xs[64][36];
    __shared__ float ws[32][NCLS_];

    const int tid  = threadIdx.x;
    const int row0 = blockIdx.x * 64;
    const int r    = tid >> 2;
    const int q    = tid & 3;

    float acc[3] = {0.f, 0.f, 0.f};

    for (int kt = 0; kt < N0_ / 32; ++kt) {
        #pragma unroll
        for (int i = 0; i < 2; ++i) {
            int id = tid + i * 256;
            int rr = id >> 3, seg = id & 7;
            float4 v = *reinterpret_cast<const float4*>(
                &x[(size_t)(row0 + rr) * N0_ + kt * 32 + seg * 4]);
            *reinterpret_cast<float4*>(&xs[rr][seg * 4]) = v;
        }
        #pragma unroll
        for (int i = 0; i < 2; ++i) {
            int id = tid + i * 256;
            if (id < 32 * NCLS_) ((float*)ws)[id] = Wcat[kt * 32 * NCLS_ + id];
        }
        __syncthreads();

        #pragma unroll 8
        for (int k = 0; k < 32; ++k) {
            float xv = xs[r][k];
            acc[0] += xv * ws[k][q];
            acc[1] += xv * ws[k][q + 4];
            acc[2] += xv * ws[k][q + 8];
        }
        __syncthreads();
    }

    float* out = y0 + (size_t)(row0 + r) * NCLS_;
    out[q]     = acc[0] + bcat[q];
    out[q + 4] = acc[1] + bcat[q + 4];
    out[q + 8] = acc[2] + bcat[q + 8];
}

// ---------------- argmax + counting sort ----------------
__global__ void zero_counts_kernel()
{
    int t = threadIdx.x;
    if (t < C_) g_cnt[t] = 0;
}

__global__ void argmax_kernel(const float* __restrict__ y1)
{
    const int warp = threadIdx.x >> 5, lane = threadIdx.x & 31;
    const int row = blockIdx.x * 4 + warp;
    const float* r = y1 + (size_t)row * C_;
    float bv = -CUDART_INF_F;
    int   bi = 0x7fffffff;
    for (int j = lane; j < C_; j += 32) {
        float v = r[j];
        if (v > bv || (v == bv && j < bi)) { bv = v; bi = j; }
    }
    #pragma unroll
    for (int o = 16; o; o >>= 1) {
        float ov = __shfl_down_sync(0xffffffffu, bv, o);
        int   oi = __shfl_down_sync(0xffffffffu, bi, o);
        if (ov > bv || (ov == bv && oi < bi)) { bv = ov; bi = oi; }
    }
    if (lane == 0) {
        g_idx[row] = bi;
        atomicAdd(&g_cnt[bi], 1);
    }
}

__global__ void prefix_kernel()
{
    if (threadIdx.x == 0) {
        int s = 0;
        for (int c = 0; c < C_; ++c) {
            g_off[c] = s;
            g_pos[c] = s;
            s += g_cnt[c];
        }
        g_off[C_] = s;
    }
}

__global__ void scatter_kernel()
{
    int b = blockIdx.x * 256 + threadIdx.x;
    int c = g_idx[b];
    int p = atomicAdd(&g_pos[c], 1);
    g_order[p] = b;
}

// ---------------- grouped expert kernel ----------------
#define EB_ROWS 32
#define EB_BK   32
#define NT      16

__global__ void __launch_bounds__(256) expert_kernel(
    const float* __restrict__ x,
    const float* __restrict__ We1, const float* __restrict__ be1,
    const float* __restrict__ We2, const float* __restrict__ be2,
    float* __restrict__ y2out)
{
    const int c     = blockIdx.y;
    const int chunk = blockIdx.x;
    const int start = g_off[c] + chunk * EB_ROWS;
    const int end   = g_off[c + 1];
    if (start >= end) return;

    __shared__ int   rs[EB_ROWS];
    __shared__ float Xs[EB_ROWS][EB_BK + 1];
    __shared__ float Ws[EB_BK * N3_ + 64];
    __shared__ float He[EB_ROWS][N3_ + 1];
    __shared__ float W2s[N3_ * NDIM_ + 4];

    const int tid  = threadIdx.x;
    const int lane = tid & 31;
    const int warp = tid >> 5;

    if (tid < EB_ROWS) rs[tid] = (start + tid < end) ? g_order[start + tid] : -1;
    for (int i = tid; i < N3_ * NDIM_; i += 256) W2s[i] = We2[(size_t)c * N3_ * NDIM_ + i];
    __syncthreads();

    const int nBase = warp * NT;
    float acc[NT];
    #pragma unroll
    for (int j = 0; j < NT; ++j) acc[j] = 0.f;

    const float* W1c = We1 + (size_t)c * N0_ * N3_;
    const float4* Ws4 = reinterpret_cast<const float4*>(Ws);

    for (int kt = 0; kt < N0_ / EB_BK; ++kt) {
        {
            int r  = tid >> 3;
            int k4 = (tid & 7) * 4;
            int rb = rs[r];
            float4 v = make_float4(0.f, 0.f, 0.f, 0.f);
            if (rb >= 0)
                v = *reinterpret_cast<const float4*>(&x[(size_t)rb * N0_ + kt * EB_BK + k4]);
            Xs[r][k4 + 0] = v.x; Xs[r][k4 + 1] = v.y;
            Xs[r][k4 + 2] = v.z; Xs[r][k4 + 3] = v.w;
        }
        {
            const float4* src = reinterpret_cast<const float4*>(W1c + (size_t)kt * EB_BK * N3_);
            float4* dst = reinterpret_cast<float4*>(Ws);
            #pragma unroll
            for (int i = 0; i < 4; ++i) {
                int id = tid + i * 256;
                if (id < (EB_BK * N3_) / 4) dst[id] = src[id];
            }
        }
        __syncthreads();

        #pragma unroll 4
        for (int k = 0; k < EB_BK; ++k) {
            float a = Xs[lane][k];
            #pragma unroll
            for (int j4 = 0; j4 < NT / 4; ++j4) {
                float4 wv = Ws4[(k * N3_ + nBase) / 4 + j4];
                acc[j4 * 4 + 0] += a * wv.x;
                acc[j4 * 4 + 1] += a * wv.y;
                acc[j4 * 4 + 2] += a * wv.z;
                acc[j4 * 4 + 3] += a * wv.w;
            }
        }
        __syncthreads();
    }

    #pragma unroll
    for (int j = 0; j < NT; ++j) {
        int n = nBase + j;
        if (n < N3_)
            He[lane][n] = fmaxf(acc[j] + be1[(size_t)c * N3_ + n], 0.f);
    }
    __syncthreads();

    if (tid < EB_ROWS * NDIM_) {
        int r = tid / NDIM_, d = tid % NDIM_;
        int rb = rs[r];
        if (rb >= 0) {
            float s = 0.f;
            #pragma unroll 4
            for (int k = 0; k < N3_; ++k) s += He[r][k] * W2s[k * NDIM_ + d];
            y2out[(size_t)rb * NDIM_ + d] = s + be2[(size_t)c * NDIM_ + d];
        }
    }
}

// ---------------- launch ----------------
extern "C" void kernel_launch(void* const* d_in, const int* in_sizes, int n_in,
                              void* d_out, int out_size)
{
    const float* x    = (const float*)d_in[0];
    const float* Wcat = (const float*)d_in[1];
    const float* bcat = (const float*)d_in[2];
    const float* Wb1  = (const float*)d_in[3];
    const float* bb1  = (const float*)d_in[4];
    const float* Wb2  = (const float*)d_in[5];
    const float* bb2  = (const float*)d_in[6];
    const float* Wb3  = (const float*)d_in[7];
    const float* bb3  = (const float*)d_in[8];
    const float* We1  = (const float*)d_in[9];
    const float* be1  = (const float*)d_in[10];
    const float* We2  = (const float*)d_in[11];
    const float* be2  = (const float*)d_in[12];
    float* out = (float*)d_out;

    uint32_t *xp, *w1t, *h1p, *w2t, *h2p, *w3t;
    cudaGetSymbolAddress((void**)&xp,  g_xp);
    cudaGetSymbolAddress((void**)&w1t, g_w1t);
    cudaGetSymbolAddress((void**)&h1p, g_h1p);
    cudaGetSymbolAddress((void**)&w2t, g_w2t);
    cudaGetSymbolAddress((void**)&h2p, g_h2p);
    cudaGetSymbolAddress((void**)&w3t, g_w3t);

    // preprocessing: pack x, transpose+pack weights
    split_pack_kernel<<<(B_ * N0_ + 255) / 256, 256>>>(x, xp, B_ * N0_);
    {
        dim3 blk(32, 8);
        transpose_split_pack_kernel<<<dim3(N0_ / 32, N1P / 32), blk>>>(Wb1, w1t, N0_, N1_, N0_, N1P);
        transpose_split_pack_kernel<<<dim3(N1P / 32, N2P / 32), blk>>>(Wb2, w2t, N1_, N2_, N1P, N2P);
        transpose_split_pack_kernel<<<dim3(N2P / 32, 128 / 32), blk>>>(Wb3, w3t, N2_, C_, N2P, 128);
    }

    // bin head on mma.sync tensor cores
    mma_gemm_kernel<1, true><<<dim3(N1P / 64, B_ / 128), 256>>>(
        xp, w1t, bb1, nullptr, h1p, 0, N1_, N1P, N0_);
    mma_gemm_kernel<1, true><<<dim3(N2P / 64, B_ / 128), 256>>>(
        h1p, w2t, bb2, nullptr, h2p, 0, N2_, N2P, N1P);
    mma_gemm_kernel<0, false><<<dim3(128 / 64, B_ / 128), 256>>>(
        h2p, w3t, bb3, out + OUT_Y1, nullptr, C_, C_, 128, N2P);

    // category head
    y0_kernel<<<B_ / 64, 256>>>(x, Wcat, bcat, out + OUT_Y0);

    // argmax + counting sort
    zero_counts_kernel<<<1, 128>>>();
    argmax_kernel<<<B_ / 4, 128>>>(out + OUT_Y1);
    prefix_kernel<<<1, 32>>>();
    scatter_kernel<<<B_ / 256, 256>>>();

    // selected-expert evaluation
    {
        dim3 grid(B_ / EB_ROWS, C_);
        expert_kernel<<<grid, 256>>>(x, We1, be1, We2, be2, out + OUT_Y2);
    }
}